// round 16
// baseline (speedup 1.0000x reference)
#include <cuda_runtime.h>
#include <cuda_fp16.h>
#include <math.h>
#include <stdint.h>

// ---------------- constants ----------------
constexpr int   T       = 65536;
constexpr int   S       = 128;
constexpr int   H       = 256;
constexpr int   A       = 8;
constexpr float GAMMA_C = 0.99f;
constexpr float GL      = 0.99f * 0.95f;     // gamma * lambda
constexpr float EPSC    = 0.2f;
constexpr float LOG2PI  = 1.8378770664093453f;
constexpr int   TX      = T + 128;           // T plus bootstrap tile
constexpr unsigned int NBLK = 128;           // blocks in fused GAE/loss kernel
constexpr int   BTH     = 512;               // threads per block in gae_loss

// ---------------- device scratch (static: no allocations allowed) ----------------
__device__ __align__(16) __half g_s16[(size_t)TX * S];
__device__ __align__(16) __half g_h1v[(size_t)TX * H];
__device__ __align__(16) __half g_h1p[(size_t)TX * H];
__device__ float g_values[TX];               // [T] = bootstrap value v(sp[-1])
__device__ __align__(16) float g_mu[(size_t)T * A];
__device__ float g_Ablk[NBLK];
__device__ float g_Bblk[NBLK];
__device__ float g_stats[4];   // [0]=sum adv, [1]=sum adv^2, [2]=sum pg, [3]=sum vf
__device__ unsigned int g_arr1 = 0, g_dep1 = 0;
__device__ unsigned int g_arr2 = 0, g_dep2 = 0;
__device__ unsigned int g_tick = 0;

// transposed weights (fp16): layer1 combined [512][128]; layer2 [256][256] each
__device__ __align__(16) __half g_w1[65536];
__device__ __align__(16) __half g_w2v[65536];
__device__ __align__(16) __half g_w2p[65536];

// ---------------- HW tanh (MUFU.TANH, rel err ~2^-10.7) ----------------
__device__ __forceinline__ float tanh_hw(float x) {
    float y;
    asm("tanh.approx.f32 %0, %1;" : "=f"(y) : "f"(x));
    return y;
}

// ---------------- PTX helpers ----------------
__device__ __forceinline__ uint32_t smem_u32(const void* p) {
    return (uint32_t)__cvta_generic_to_shared(p);
}

__device__ __forceinline__ void cpasync16(uint32_t dst, const void* src) {
    asm volatile("cp.async.cg.shared.global [%0], [%1], 16;" :: "r"(dst), "l"(src));
}

#define CP_COMMIT()  asm volatile("cp.async.commit_group;")
#define CP_WAIT1()   asm volatile("cp.async.wait_group 1;" ::: "memory")

#define LDSM4(r0, r1, r2, r3, addr)                                                 \
    asm volatile("ldmatrix.sync.aligned.m8n8.x4.shared.b16 {%0,%1,%2,%3}, [%4];"    \
        : "=r"(r0), "=r"(r1), "=r"(r2), "=r"(r3) : "r"(addr))

#define MMAF16(cc, a, b0, b1)                                                       \
    asm volatile("mma.sync.aligned.m16n8k16.row.col.f32.f16.f16.f32 "               \
        "{%0,%1,%2,%3}, {%4,%5,%6,%7}, {%8,%9}, {%0,%1,%2,%3};"                     \
        : "+f"((cc)[0]), "+f"((cc)[1]), "+f"((cc)[2]), "+f"((cc)[3])                \
        : "r"((a)[0]), "r"((a)[1]), "r"((a)[2]), "r"((a)[3]), "r"(b0), "r"(b1))

// ---------------- software grid barrier (volatile-load spin; self-resetting) ----------------
__device__ __forceinline__ void grid_barrier(unsigned int* arr, unsigned int* dep)
{
    __syncthreads();
    if (threadIdx.x == 0) {
        __threadfence();
        atomicAdd(arr, 1u);
        while (*(volatile unsigned int*)arr < NBLK) { }
        __threadfence();
        unsigned int d = atomicAdd(dep, 1u);
        if (d == NBLK - 1) {            // last one out resets for next graph replay
            atomicExch(arr, 0u);
            atomicExch(dep, 0u);
        }
    }
    __syncthreads();
}

// ---------------- 3-stage cp.async GEMM mainloop (k-chunk 64, single fp16) ----------------
// Stage 32KB: A@0 (128 rows x 128B), B@16K; 3 stages. Swizzle g ^ (row&7).
// One __syncthreads per chunk; prefetch depth 2 chunks.
__device__ __forceinline__ void mma_tile(
    const uint4* __restrict__ Ap, const uint4* __restrict__ Bp,
    int KG, int nc, uint32_t s0, float c[4][4][4])
{
    const int tid = threadIdx.x;
    const int wid = tid >> 5, lane = tid & 31;
    const int mbase = (wid >> 2) * 64;
    const int nbase = (wid & 3) * 32;
    const int l7    = lane & 7;
    const int rowA  = mbase + (lane & 15);
    const int halfA = lane >> 4;
    const int rowB  = (lane & 7) + ((lane >> 4) & 1) * 8;
    const int halfB = (lane >> 3) & 1;

    auto load_chunk = [&](int st, int ch) {
        uint32_t base = s0 + (uint32_t)st * 32768u;
        int kg0 = ch * 8;
        #pragma unroll
        for (int i = 0; i < 4; i++) {
            int idx = i * 256 + tid;
            int row = idx >> 3, g = idx & 7;
            uint32_t d = base + (uint32_t)(row * 128 + ((g ^ (row & 7)) << 4));
            size_t sx = (size_t)row * KG + kg0 + g;
            cpasync16(d,          Ap + sx);
            cpasync16(d + 16384,  Bp + sx);
        }
    };

    // prologue: 2 chunks in flight (nc >= 2 always)
    load_chunk(0, 0); CP_COMMIT();
    load_chunk(1, 1); CP_COMMIT();

    for (int ch = 0; ch < nc; ch++) {
        CP_WAIT1();            // group for chunk ch complete (uniform always-commit below)
        __syncthreads();

        uint32_t base = s0 + (uint32_t)(ch % 3) * 32768u;
        #pragma unroll
        for (int ks = 0; ks < 4; ks++) {
            int kgA = 2 * ks + halfA;
            uint32_t pgA = (uint32_t)((kgA ^ l7) << 4);
            int kgB = 2 * ks + halfB;
            uint32_t pgB = (uint32_t)((kgB ^ l7) << 4);

            uint32_t ah[4][4];
            #pragma unroll
            for (int mi = 0; mi < 4; mi++) {
                uint32_t ro = base + (uint32_t)((rowA + 16 * mi) * 128) + pgA;
                LDSM4(ah[mi][0], ah[mi][1], ah[mi][2], ah[mi][3], ro);
            }
            uint32_t b[2][4];
            #pragma unroll
            for (int p = 0; p < 2; p++) {
                uint32_t ro = base + (uint32_t)((nbase + p * 16 + rowB) * 128) + pgB;
                LDSM4(b[p][0], b[p][1], b[p][2], b[p][3], ro + 16384);
            }
            #pragma unroll
            for (int mi = 0; mi < 4; mi++)
                #pragma unroll
                for (int p = 0; p < 2; p++)
                    #pragma unroll
                    for (int s2 = 0; s2 < 2; s2++)
                        MMAF16(c[mi][p * 2 + s2], ah[mi], b[p][2 * s2], b[p][2 * s2 + 1]);
        }

        // next load targets stage (ch-1)%3: its readers all passed this chunk's barrier
        if (ch + 2 < nc) load_chunk((ch + 2) % 3, ch + 2);
        CP_COMMIT();           // always commit (possibly empty) -> uniform wait semantics
    }
}

// ---------------- merged prep: input convert + weight transpose + presets + bootstrap ----------------
__global__ void prep_all(const float* __restrict__ s_in,
                         const float* __restrict__ W1v, const float* __restrict__ W1p,
                         const float* __restrict__ W2v, const float* __restrict__ W2p,
                         const float* __restrict__ sp,
                         const float* __restrict__ vhb, const float* __restrict__ mub)
{
    int gid = blockIdx.x * 256 + threadIdx.x;

    // s fp32 -> fp16 (4 floats per thread, coalesced)
    {
        float4 v = ((const float4*)s_in)[gid];
        __half2 h0, h1;
        h0.x = __float2half_rn(v.x); h0.y = __float2half_rn(v.y);
        h1.x = __float2half_rn(v.z); h1.y = __float2half_rn(v.w);
        ((__half2*)g_s16)[2 * gid]     = h0;
        ((__half2*)g_s16)[2 * gid + 1] = h1;
    }

    // weight transpose -> fp16 (196608 elements)
    if (gid < 196608) {
        const float* W; __half* Wt; int K, base, nofs;
        if (gid < 32768)       { W = W1v; Wt = g_w1;  K = 128; base = 0;      nofs = 0; }
        else if (gid < 65536)  { W = W1p; Wt = g_w1;  K = 128; base = 32768;  nofs = 256; }
        else if (gid < 131072) { W = W2v; Wt = g_w2v; K = 256; base = 65536;  nofs = 0; }
        else                   { W = W2p; Wt = g_w2p; K = 256; base = 131072; nofs = 0; }
        int j = gid - base;
        int k = j >> 8, n = (j & 255) + nofs;
        Wt[(size_t)n * K + k] = __float2half_rn(W[j]);
    }
    if (gid < TX) g_values[gid] = vhb[0];
    if (gid < T) {
        float4 m0 = *(const float4*)mub;
        float4 m1 = *(const float4*)(mub + 4);
        ((float4*)g_mu)[2 * gid]     = m0;
        ((float4*)g_mu)[2 * gid + 1] = m1;
    }
    if (gid < 128) {
        g_s16[(size_t)T * S + gid] = __float2half_rn(sp[(size_t)(T - 1) * S + gid]);
    }
}

#define SMEM_SZ (98304 + 512 + 4096)

// ---------------- layer 1 fused (v+p), N=512, M=T+128 ----------------
__global__ void __launch_bounds__(256, 2) gemm_l1(
    const float* __restrict__ vb1, const float* __restrict__ pib1)
{
    extern __shared__ char smem[];
    const uint32_t s0 = smem_u32(smem);
    float* bias_s = (float*)(smem + 98304);

    const int tid = threadIdx.x;
    const int wid = tid >> 5, lane = tid & 31;
    const int n0 = blockIdx.x * 128;    // 0..383 over combined 512
    const int m0 = blockIdx.y * 128;
    const int mbase = (wid >> 2) * 64;
    const int nbase = (wid & 3) * 32;

    if (tid < 128) bias_s[tid] = (n0 < 256) ? vb1[n0 + tid] : pib1[n0 - 256 + tid];

    float c[4][4][4] = {};
    mma_tile((const uint4*)g_s16 + (size_t)m0 * 16,
             (const uint4*)g_w1 + (size_t)n0 * 16, 16, 2, s0, c);

    __half* Yh; int nb;
    if (n0 < 256) { Yh = g_h1v; nb = n0; }
    else          { Yh = g_h1p; nb = n0 - 256; }

    const int g = lane >> 2, tq = lane & 3;
    #pragma unroll
    for (int mi = 0; mi < 4; mi++) {
        int row = m0 + mbase + mi * 16 + g;
        #pragma unroll
        for (int ni = 0; ni < 4; ni++) {
            int colb = nbase + ni * 8 + 2 * tq;
            int col  = nb + colb;
            float b0 = bias_s[colb], b1 = bias_s[colb + 1];
            __half2 hA, hB;
            hA.x = __float2half_rn(tanh_hw(c[mi][ni][0] + b0));
            hA.y = __float2half_rn(tanh_hw(c[mi][ni][1] + b1));
            hB.x = __float2half_rn(tanh_hw(c[mi][ni][2] + b0));
            hB.y = __float2half_rn(tanh_hw(c[mi][ni][3] + b1));
            *(__half2*)(Yh + (size_t)row * 256 + col)       = hA;
            *(__half2*)(Yh + (size_t)(row + 8) * 256 + col) = hB;
        }
    }
}

// ---------------- layer 2 merged (z=0: v-net + value head, z=1: p-net + mu head) ----------------
__global__ void __launch_bounds__(256, 2) gemm_l2(
    const float* __restrict__ vb2, const float* __restrict__ pib2,
    const float* __restrict__ vhW, const float* __restrict__ muW)
{
    const int z = blockIdx.z;
    if (z == 1 && blockIdx.y == gridDim.y - 1) return;   // p-net: no bootstrap tile

    extern __shared__ char smem[];
    const uint32_t s0 = smem_u32(smem);
    float* bias_s = (float*)(smem + 98304);
    float* hW_s   = (float*)(smem + 98304 + 512);

    const int tid = threadIdx.x;
    const int wid = tid >> 5, lane = tid & 31;
    const int n0 = blockIdx.x * 128;
    const int m0 = blockIdx.y * 128;
    const int mbase = (wid >> 2) * 64;
    const int nbase = (wid & 3) * 32;

    const __half *Ah, *Bp;
    if (z == 0) {
        Ah = g_h1v; Bp = g_w2v;
        if (tid < 128) bias_s[tid] = vb2[n0 + tid];
        if (tid < 128) hW_s[tid]   = vhW[n0 + tid];
    } else {
        Ah = g_h1p; Bp = g_w2p;
        if (tid < 128) bias_s[tid] = pib2[n0 + tid];
        for (int i = tid; i < 1024; i += 256) hW_s[i] = muW[n0 * 8 + i];
    }

    float c[4][4][4] = {};
    mma_tile((const uint4*)Ah + (size_t)m0 * 32,
             (const uint4*)Bp + (size_t)n0 * 32, 32, 4, s0, c);

    const int g = lane >> 2, tq = lane & 3;
    if (z == 0) {
        #pragma unroll
        for (int mi = 0; mi < 4; mi++) {
            float pv0 = 0.f, pv1 = 0.f;
            #pragma unroll
            for (int ni = 0; ni < 4; ni++) {
                int colb = nbase + ni * 8 + 2 * tq;
                float b0 = bias_s[colb], b1 = bias_s[colb + 1];
                float w0 = hW_s[colb],   w1 = hW_s[colb + 1];
                pv0 += tanh_hw(c[mi][ni][0] + b0) * w0 + tanh_hw(c[mi][ni][1] + b1) * w1;
                pv1 += tanh_hw(c[mi][ni][2] + b0) * w0 + tanh_hw(c[mi][ni][3] + b1) * w1;
            }
            pv0 += __shfl_xor_sync(0xffffffffu, pv0, 1);
            pv0 += __shfl_xor_sync(0xffffffffu, pv0, 2);
            pv1 += __shfl_xor_sync(0xffffffffu, pv1, 1);
            pv1 += __shfl_xor_sync(0xffffffffu, pv1, 2);
            if (tq == 0) {
                int row = m0 + mbase + mi * 16 + g;
                atomicAdd(&g_values[row],     pv0);
                atomicAdd(&g_values[row + 8], pv1);
            }
        }
    } else {
        #pragma unroll
        for (int mi = 0; mi < 4; mi++) {
            float pm0[8] = {}, pm1[8] = {};
            #pragma unroll
            for (int ni = 0; ni < 4; ni++) {
                int colb = nbase + ni * 8 + 2 * tq;
                float b0 = bias_s[colb], b1 = bias_s[colb + 1];
                float t0 = tanh_hw(c[mi][ni][0] + b0);
                float t1 = tanh_hw(c[mi][ni][1] + b1);
                float t2 = tanh_hw(c[mi][ni][2] + b0);
                float t3 = tanh_hw(c[mi][ni][3] + b1);
                #pragma unroll
                for (int j = 0; j < 8; j++) {
                    float w0 = hW_s[colb * 8 + j], w1 = hW_s[(colb + 1) * 8 + j];
                    pm0[j] += t0 * w0 + t1 * w1;
                    pm1[j] += t2 * w0 + t3 * w1;
                }
            }
            #pragma unroll
            for (int j = 0; j < 8; j++) {
                pm0[j] += __shfl_xor_sync(0xffffffffu, pm0[j], 1);
                pm0[j] += __shfl_xor_sync(0xffffffffu, pm0[j], 2);
                pm1[j] += __shfl_xor_sync(0xffffffffu, pm1[j], 1);
                pm1[j] += __shfl_xor_sync(0xffffffffu, pm1[j], 2);
            }
            if (tq == 0) {
                int row = m0 + mbase + mi * 16 + g;
                #pragma unroll
                for (int j = 0; j < 8; j++) {
                    atomicAdd(&g_mu[(size_t)row * 8 + j],       pm0[j]);
                    atomicAdd(&g_mu[(size_t)(row + 8) * 8 + j], pm1[j]);
                }
            }
        }
    }
}

// ---------------- fused GAE scan + loss (128 blocks x 512, vectorized loads) ----------------
__global__ void __launch_bounds__(BTH) gae_loss(
    const float* __restrict__ r, const float* __restrict__ dmask,
    const float* __restrict__ a, const float* __restrict__ lpo,
    const float* __restrict__ logstd, float* __restrict__ out)
{
    const int u = blockIdx.x * BTH + threadIdx.x;
    const int t = T - 1 - u;
    const int lane = threadIdx.x & 31, warp = threadIdx.x >> 5;   // 16 warps

    // ---- phase 1: per-thread composite, block-level scan ----
    float m  = dmask[t];
    float nv = g_values[t + 1];                          // [T] = bootstrap
    float bb = r[t] + GAMMA_C * nv * m - g_values[t];    // delta
    float aa = GL * m;

    #pragma unroll
    for (int off = 1; off < 32; off <<= 1) {
        float ap = __shfl_up_sync(0xffffffffu, aa, off);
        float bp = __shfl_up_sync(0xffffffffu, bb, off);
        if (lane >= off) { bb = fmaf(aa, bp, bb); aa *= ap; }
    }
    __shared__ float wA[32], wB[32];
    if (lane == 31) { wA[warp] = aa; wB[warp] = bb; }
    __syncthreads();
    if (warp == 0) {
        float a2 = (lane < 16) ? wA[lane] : 1.f;
        float b2 = (lane < 16) ? wB[lane] : 0.f;
        #pragma unroll
        for (int off = 1; off < 16; off <<= 1) {
            float ap = __shfl_up_sync(0xffffffffu, a2, off);
            float bp = __shfl_up_sync(0xffffffffu, b2, off);
            if (lane >= off) { b2 = fmaf(a2, bp, b2); a2 *= ap; }
        }
        if (lane < 16) { wA[lane] = a2; wB[lane] = b2; }
    }
    __syncthreads();
    if (warp > 0) {
        float pa = wA[warp - 1], pb = wB[warp - 1];
        bb = fmaf(aa, pb, bb);
        aa *= pa;
    }
    if (threadIdx.x == BTH - 1) { g_Ablk[blockIdx.x] = aa; g_Bblk[blockIdx.x] = bb; }

    // ---- barrier 1: all block composites visible ----
    grid_barrier(&g_arr1, &g_dep1);

    // each block computes its own incoming prefix Gin
    __shared__ float ginS;
    if (threadIdx.x == 0) {
        float g = 0.f;
        for (int j = 0; j < blockIdx.x; j++) g = fmaf(g_Ablk[j], g, g_Bblk[j]);
        ginS = g;
    }
    __syncthreads();
    const float adv = fmaf(aa, ginS, bb);

    // ---- phase 2: adv stats ----
    {
        float s1 = adv, s2 = adv * adv;
        #pragma unroll
        for (int o = 16; o; o >>= 1) {
            s1 += __shfl_down_sync(0xffffffffu, s1, o);
            s2 += __shfl_down_sync(0xffffffffu, s2, o);
        }
        if (lane == 0) { wA[warp] = s1; wB[warp] = s2; }
        __syncthreads();
        if (warp == 0) {
            float t1 = (lane < 16) ? wA[lane] : 0.f;
            float t2 = (lane < 16) ? wB[lane] : 0.f;
            #pragma unroll
            for (int o = 8; o; o >>= 1) {
                t1 += __shfl_down_sync(0xffffu, t1, o);
                t2 += __shfl_down_sync(0xffffu, t2, o);
            }
            if (lane == 0) {
                atomicAdd(&g_stats[0], t1);
                atomicAdd(&g_stats[1], t2);
            }
        }
        __syncthreads();   // wA/wB reused below
    }

    // ---- barrier 2: stats complete ----
    grid_barrier(&g_arr2, &g_dep2);

    float mean = g_stats[0] * (1.f / (float)T);
    float var  = (g_stats[1] - (float)T * mean * mean) * (1.f / (float)(T - 1));
    float sd   = sqrtf(fmaxf(var, 0.f));

    // ---- phase 3: loss terms (vectorized float4 loads for mu and a) ----
    float lp = 0.f;
    {
        const float4* mup = (const float4*)(g_mu + (size_t)t * 8);
        const float4* ap4 = (const float4*)(a    + (size_t)t * 8);
        float4 mu0 = mup[0], mu1 = mup[1];
        float4 a0  = ap4[0], a1  = ap4[1];
        float muv[8] = {mu0.x, mu0.y, mu0.z, mu0.w, mu1.x, mu1.y, mu1.z, mu1.w};
        float av[8]  = {a0.x,  a0.y,  a0.z,  a0.w,  a1.x,  a1.y,  a1.z,  a1.w};
        #pragma unroll
        for (int j = 0; j < A; j++) {
            float ls = logstd[j];
            float d  = (av[j] - muv[j]) * __expf(-ls);
            lp += -0.5f * d * d - ls;
        }
    }
    lp -= 0.5f * LOG2PI * (float)A;
    float rt = __expf(lp - lpo[t]);

    float advn = (adv - mean) / (sd + 1e-8f);
    float clip = fminf(fmaxf(rt, 1.f - EPSC), 1.f + EPSC);
    float pg   = -fminf(rt * advn, clip * advn);
    float ax   = fabsf(adv);
    float vf   = (ax < 1.f) ? 0.5f * adv * adv : ax - 0.5f;

    #pragma unroll
    for (int o = 16; o; o >>= 1) {
        pg += __shfl_down_sync(0xffffffffu, pg, o);
        vf += __shfl_down_sync(0xffffffffu, vf, o);
    }
    if (lane == 0) { wA[warp] = pg; wB[warp] = vf; }
    __syncthreads();
    if (warp == 0) {
        float t1 = (lane < 16) ? wA[lane] : 0.f;
        float t2 = (lane < 16) ? wB[lane] : 0.f;
        #pragma unroll
        for (int o = 8; o; o >>= 1) {
            t1 += __shfl_down_sync(0xffffu, t1, o);
            t2 += __shfl_down_sync(0xffffu, t2, o);
        }
        if (lane == 0) {
            atomicAdd(&g_stats[2], t1);
            atomicAdd(&g_stats[3], t2);
        }
    }
    __syncthreads();

    // ---- ticket finalize: last block to pass here sees all stat-atomics ----
    if (threadIdx.x == 0) {
        __threadfence();
        unsigned int tk = atomicAdd(&g_tick, 1u);
        if (tk == NBLK - 1) {
            float ent = 0.f;
            #pragma unroll
            for (int j = 0; j < A; j++) ent += 0.5f + 0.5f * LOG2PI + logstd[j];
            ent *= (1.f / (float)A);
            out[0] = g_stats[2] * (1.f / (float)T)
                   + 0.5f * g_stats[3] * (1.f / (float)T)
                   - 0.01f * ent;
            // reset accumulators + ticket for the next graph replay
            g_stats[0] = 0.f; g_stats[1] = 0.f; g_stats[2] = 0.f; g_stats[3] = 0.f;
            __threadfence();
            atomicExch(&g_tick, 0u);
        }
    }
}

// ---------------- launch ----------------
extern "C" void kernel_launch(void* const* d_in, const int* in_sizes, int n_in,
                              void* d_out, int out_size)
{
    const float* s_in  = (const float*)d_in[0];
    const float* a_in  = (const float*)d_in[1];
    const float* r_in  = (const float*)d_in[2];
    const float* sp_in = (const float*)d_in[3];
    const float* lpo   = (const float*)d_in[4];
    const float* dmask = (const float*)d_in[5];
    const float* piW1  = (const float*)d_in[6];
    const float* pib1  = (const float*)d_in[7];
    const float* piW2  = (const float*)d_in[8];
    const float* pib2  = (const float*)d_in[9];
    const float* muW   = (const float*)d_in[10];
    const float* mub   = (const float*)d_in[11];
    const float* lstd  = (const float*)d_in[12];
    const float* vW1   = (const float*)d_in[13];
    const float* vb1   = (const float*)d_in[14];
    const float* vW2   = (const float*)d_in[15];
    const float* vb2   = (const float*)d_in[16];
    const float* vhW   = (const float*)d_in[17];
    const float* vhb   = (const float*)d_in[18];
    float* out = (float*)d_out;

    cudaFuncSetAttribute(gemm_l1, cudaFuncAttributeMaxDynamicSharedMemorySize, SMEM_SZ);
    cudaFuncSetAttribute(gemm_l2, cudaFuncAttributeMaxDynamicSharedMemorySize, SMEM_SZ);

    // merged prep (input convert + weights + presets + bootstrap)
    prep_all<<<(T * S / 4) / 256, 256>>>(s_in, vW1, piW1, vW2, piW2, sp_in, vhb, mub);

    // layer 1: fused v+p, N=512, M includes bootstrap tile
    gemm_l1<<<dim3(4, T / 128 + 1), 256, SMEM_SZ>>>(vb1, pib1);
    // layer 2: merged v/p with fused heads (h2 never touches DRAM)
    gemm_l2<<<dim3(2, T / 128 + 1, 2), 256, SMEM_SZ>>>(vb2, pib2, vhW, muW);

    // fused GAE scan + normalization + PPO loss + finalize (one kernel)
    gae_loss<<<NBLK, BTH>>>(r_in, dmask, a_in, lpo, lstd, out);
}

// round 17
// speedup vs baseline: 1.0131x; 1.0131x over previous
#include <cuda_runtime.h>
#include <cuda_fp16.h>
#include <math.h>
#include <stdint.h>

// ---------------- constants ----------------
constexpr int   T       = 65536;
constexpr int   S       = 128;
constexpr int   H       = 256;
constexpr int   A       = 8;
constexpr float GAMMA_C = 0.99f;
constexpr float GL      = 0.99f * 0.95f;     // gamma * lambda
constexpr float EPSC    = 0.2f;
constexpr float LOG2PI  = 1.8378770664093453f;
constexpr int   TX      = T + 128;           // T plus bootstrap tile
constexpr unsigned int NBLK = 128;           // blocks in fused GAE/loss kernel
constexpr int   BTH     = 256;               // threads per block in gae_loss
constexpr int   EPT     = 2;                 // elements (timesteps) per thread

// ---------------- device scratch (static: no allocations allowed) ----------------
__device__ __align__(16) __half g_s16[(size_t)TX * S];
__device__ __align__(16) __half g_h1v[(size_t)TX * H];
__device__ __align__(16) __half g_h1p[(size_t)TX * H];
__device__ float g_values[TX];               // [T] = bootstrap value v(sp[-1])
__device__ __align__(16) float g_mu[(size_t)T * A];
__device__ float g_Ablk[NBLK];
__device__ float g_Bblk[NBLK];
__device__ float g_stats[4];   // [0]=sum adv, [1]=sum adv^2, [2]=sum pg, [3]=sum vf
__device__ unsigned int g_arr1 = 0, g_dep1 = 0;
__device__ unsigned int g_arr2 = 0, g_dep2 = 0;
__device__ unsigned int g_tick = 0;

// transposed weights (fp16): layer1 combined [512][128]; layer2 [256][256] each
__device__ __align__(16) __half g_w1[65536];
__device__ __align__(16) __half g_w2v[65536];
__device__ __align__(16) __half g_w2p[65536];

// ---------------- HW tanh (MUFU.TANH, rel err ~2^-10.7) ----------------
__device__ __forceinline__ float tanh_hw(float x) {
    float y;
    asm("tanh.approx.f32 %0, %1;" : "=f"(y) : "f"(x));
    return y;
}

// ---------------- PTX helpers ----------------
__device__ __forceinline__ uint32_t smem_u32(const void* p) {
    return (uint32_t)__cvta_generic_to_shared(p);
}

__device__ __forceinline__ void cpasync16(uint32_t dst, const void* src) {
    asm volatile("cp.async.cg.shared.global [%0], [%1], 16;" :: "r"(dst), "l"(src));
}

#define CP_COMMIT()  asm volatile("cp.async.commit_group;")
#define CP_WAIT1()   asm volatile("cp.async.wait_group 1;" ::: "memory")

#define LDSM4(r0, r1, r2, r3, addr)                                                 \
    asm volatile("ldmatrix.sync.aligned.m8n8.x4.shared.b16 {%0,%1,%2,%3}, [%4];"    \
        : "=r"(r0), "=r"(r1), "=r"(r2), "=r"(r3) : "r"(addr))

#define MMAF16(cc, a, b0, b1)                                                       \
    asm volatile("mma.sync.aligned.m16n8k16.row.col.f32.f16.f16.f32 "               \
        "{%0,%1,%2,%3}, {%4,%5,%6,%7}, {%8,%9}, {%0,%1,%2,%3};"                     \
        : "+f"((cc)[0]), "+f"((cc)[1]), "+f"((cc)[2]), "+f"((cc)[3])                \
        : "r"((a)[0]), "r"((a)[1]), "r"((a)[2]), "r"((a)[3]), "r"(b0), "r"(b1))

// ---------------- software grid barrier (volatile-load spin; self-resetting) ----------------
__device__ __forceinline__ void grid_barrier(unsigned int* arr, unsigned int* dep)
{
    __syncthreads();
    if (threadIdx.x == 0) {
        __threadfence();
        atomicAdd(arr, 1u);
        while (*(volatile unsigned int*)arr < NBLK) { }
        __threadfence();
        unsigned int d = atomicAdd(dep, 1u);
        if (d == NBLK - 1) {            // last one out resets for next graph replay
            atomicExch(arr, 0u);
            atomicExch(dep, 0u);
        }
    }
    __syncthreads();
}

// ---------------- 3-stage cp.async GEMM mainloop (k-chunk 64, single fp16) ----------------
// Stage 32KB: A@0 (128 rows x 128B), B@16K; 3 stages. Swizzle g ^ (row&7).
// One __syncthreads per chunk; prefetch depth 2 chunks.
__device__ __forceinline__ void mma_tile(
    const uint4* __restrict__ Ap, const uint4* __restrict__ Bp,
    int KG, int nc, uint32_t s0, float c[4][4][4])
{
    const int tid = threadIdx.x;
    const int wid = tid >> 5, lane = tid & 31;
    const int mbase = (wid >> 2) * 64;
    const int nbase = (wid & 3) * 32;
    const int l7    = lane & 7;
    const int rowA  = mbase + (lane & 15);
    const int halfA = lane >> 4;
    const int rowB  = (lane & 7) + ((lane >> 4) & 1) * 8;
    const int halfB = (lane >> 3) & 1;

    auto load_chunk = [&](int st, int ch) {
        uint32_t base = s0 + (uint32_t)st * 32768u;
        int kg0 = ch * 8;
        #pragma unroll
        for (int i = 0; i < 4; i++) {
            int idx = i * 256 + tid;
            int row = idx >> 3, g = idx & 7;
            uint32_t d = base + (uint32_t)(row * 128 + ((g ^ (row & 7)) << 4));
            size_t sx = (size_t)row * KG + kg0 + g;
            cpasync16(d,          Ap + sx);
            cpasync16(d + 16384,  Bp + sx);
        }
    };

    // prologue: 2 chunks in flight (nc >= 2 always)
    load_chunk(0, 0); CP_COMMIT();
    load_chunk(1, 1); CP_COMMIT();

    for (int ch = 0; ch < nc; ch++) {
        CP_WAIT1();            // group for chunk ch complete (uniform always-commit below)
        __syncthreads();

        uint32_t base = s0 + (uint32_t)(ch % 3) * 32768u;
        #pragma unroll
        for (int ks = 0; ks < 4; ks++) {
            int kgA = 2 * ks + halfA;
            uint32_t pgA = (uint32_t)((kgA ^ l7) << 4);
            int kgB = 2 * ks + halfB;
            uint32_t pgB = (uint32_t)((kgB ^ l7) << 4);

            uint32_t ah[4][4];
            #pragma unroll
            for (int mi = 0; mi < 4; mi++) {
                uint32_t ro = base + (uint32_t)((rowA + 16 * mi) * 128) + pgA;
                LDSM4(ah[mi][0], ah[mi][1], ah[mi][2], ah[mi][3], ro);
            }
            uint32_t b[2][4];
            #pragma unroll
            for (int p = 0; p < 2; p++) {
                uint32_t ro = base + (uint32_t)((nbase + p * 16 + rowB) * 128) + pgB;
                LDSM4(b[p][0], b[p][1], b[p][2], b[p][3], ro + 16384);
            }
            #pragma unroll
            for (int mi = 0; mi < 4; mi++)
                #pragma unroll
                for (int p = 0; p < 2; p++)
                    #pragma unroll
                    for (int s2 = 0; s2 < 2; s2++)
                        MMAF16(c[mi][p * 2 + s2], ah[mi], b[p][2 * s2], b[p][2 * s2 + 1]);
        }

        // next load targets stage (ch-1)%3: its readers all passed this chunk's barrier
        if (ch + 2 < nc) load_chunk((ch + 2) % 3, ch + 2);
        CP_COMMIT();           // always commit (possibly empty) -> uniform wait semantics
    }
}

// ---------------- merged prep: input convert + weight transpose + presets + bootstrap ----------------
// grid 4096 x 256: each thread converts 8 floats (2 x float4) of s; subranges do the rest.
__global__ void prep_all(const float* __restrict__ s_in,
                         const float* __restrict__ W1v, const float* __restrict__ W1p,
                         const float* __restrict__ W2v, const float* __restrict__ W2p,
                         const float* __restrict__ sp,
                         const float* __restrict__ vhb, const float* __restrict__ mub)
{
    int gid = blockIdx.x * 256 + threadIdx.x;   // 0 .. 1048575

    // s fp32 -> fp16, 8 floats per thread (2 independent float4 loads in flight)
    {
        float4 v0 = ((const float4*)s_in)[2 * gid];
        float4 v1 = ((const float4*)s_in)[2 * gid + 1];
        __half2 h0, h1, h2, h3;
        h0.x = __float2half_rn(v0.x); h0.y = __float2half_rn(v0.y);
        h1.x = __float2half_rn(v0.z); h1.y = __float2half_rn(v0.w);
        h2.x = __float2half_rn(v1.x); h2.y = __float2half_rn(v1.y);
        h3.x = __float2half_rn(v1.z); h3.y = __float2half_rn(v1.w);
        ((__half2*)g_s16)[4 * gid]     = h0;
        ((__half2*)g_s16)[4 * gid + 1] = h1;
        ((__half2*)g_s16)[4 * gid + 2] = h2;
        ((__half2*)g_s16)[4 * gid + 3] = h3;
    }

    // weight transpose -> fp16 (196608 elements)
    if (gid < 196608) {
        const float* W; __half* Wt; int K, base, nofs;
        if (gid < 32768)       { W = W1v; Wt = g_w1;  K = 128; base = 0;      nofs = 0; }
        else if (gid < 65536)  { W = W1p; Wt = g_w1;  K = 128; base = 32768;  nofs = 256; }
        else if (gid < 131072) { W = W2v; Wt = g_w2v; K = 256; base = 65536;  nofs = 0; }
        else                   { W = W2p; Wt = g_w2p; K = 256; base = 131072; nofs = 0; }
        int j = gid - base;
        int k = j >> 8, n = (j & 255) + nofs;
        Wt[(size_t)n * K + k] = __float2half_rn(W[j]);
    }
    if (gid < TX) g_values[gid] = vhb[0];
    if (gid < T) {
        float4 m0 = *(const float4*)mub;
        float4 m1 = *(const float4*)(mub + 4);
        ((float4*)g_mu)[2 * gid]     = m0;
        ((float4*)g_mu)[2 * gid + 1] = m1;
    }
    if (gid < 128) {
        g_s16[(size_t)T * S + gid] = __float2half_rn(sp[(size_t)(T - 1) * S + gid]);
    }
}

#define SMEM_SZ (98304 + 512 + 4096)

// ---------------- layer 1 fused (v+p), N=512, M=T+128 ----------------
__global__ void __launch_bounds__(256, 2) gemm_l1(
    const float* __restrict__ vb1, const float* __restrict__ pib1)
{
    extern __shared__ char smem[];
    const uint32_t s0 = smem_u32(smem);
    float* bias_s = (float*)(smem + 98304);

    const int tid = threadIdx.x;
    const int wid = tid >> 5, lane = tid & 31;
    const int n0 = blockIdx.x * 128;    // 0..383 over combined 512
    const int m0 = blockIdx.y * 128;
    const int mbase = (wid >> 2) * 64;
    const int nbase = (wid & 3) * 32;

    if (tid < 128) bias_s[tid] = (n0 < 256) ? vb1[n0 + tid] : pib1[n0 - 256 + tid];

    float c[4][4][4] = {};
    mma_tile((const uint4*)g_s16 + (size_t)m0 * 16,
             (const uint4*)g_w1 + (size_t)n0 * 16, 16, 2, s0, c);

    __half* Yh; int nb;
    if (n0 < 256) { Yh = g_h1v; nb = n0; }
    else          { Yh = g_h1p; nb = n0 - 256; }

    const int g = lane >> 2, tq = lane & 3;
    #pragma unroll
    for (int mi = 0; mi < 4; mi++) {
        int row = m0 + mbase + mi * 16 + g;
        #pragma unroll
        for (int ni = 0; ni < 4; ni++) {
            int colb = nbase + ni * 8 + 2 * tq;
            int col  = nb + colb;
            float b0 = bias_s[colb], b1 = bias_s[colb + 1];
            __half2 hA, hB;
            hA.x = __float2half_rn(tanh_hw(c[mi][ni][0] + b0));
            hA.y = __float2half_rn(tanh_hw(c[mi][ni][1] + b1));
            hB.x = __float2half_rn(tanh_hw(c[mi][ni][2] + b0));
            hB.y = __float2half_rn(tanh_hw(c[mi][ni][3] + b1));
            *(__half2*)(Yh + (size_t)row * 256 + col)       = hA;
            *(__half2*)(Yh + (size_t)(row + 8) * 256 + col) = hB;
        }
    }
}

// ---------------- layer 2 merged (z=0: v-net + value head, z=1: p-net + mu head) ----------------
__global__ void __launch_bounds__(256, 2) gemm_l2(
    const float* __restrict__ vb2, const float* __restrict__ pib2,
    const float* __restrict__ vhW, const float* __restrict__ muW)
{
    const int z = blockIdx.z;
    if (z == 1 && blockIdx.y == gridDim.y - 1) return;   // p-net: no bootstrap tile

    extern __shared__ char smem[];
    const uint32_t s0 = smem_u32(smem);
    float* bias_s = (float*)(smem + 98304);
    float* hW_s   = (float*)(smem + 98304 + 512);

    const int tid = threadIdx.x;
    const int wid = tid >> 5, lane = tid & 31;
    const int n0 = blockIdx.x * 128;
    const int m0 = blockIdx.y * 128;
    const int mbase = (wid >> 2) * 64;
    const int nbase = (wid & 3) * 32;

    const __half *Ah, *Bp;
    if (z == 0) {
        Ah = g_h1v; Bp = g_w2v;
        if (tid < 128) bias_s[tid] = vb2[n0 + tid];
        if (tid < 128) hW_s[tid]   = vhW[n0 + tid];
    } else {
        Ah = g_h1p; Bp = g_w2p;
        if (tid < 128) bias_s[tid] = pib2[n0 + tid];
        for (int i = tid; i < 1024; i += 256) hW_s[i] = muW[n0 * 8 + i];
    }

    float c[4][4][4] = {};
    mma_tile((const uint4*)Ah + (size_t)m0 * 32,
             (const uint4*)Bp + (size_t)n0 * 32, 32, 4, s0, c);

    const int g = lane >> 2, tq = lane & 3;
    if (z == 0) {
        #pragma unroll
        for (int mi = 0; mi < 4; mi++) {
            float pv0 = 0.f, pv1 = 0.f;
            #pragma unroll
            for (int ni = 0; ni < 4; ni++) {
                int colb = nbase + ni * 8 + 2 * tq;
                float b0 = bias_s[colb], b1 = bias_s[colb + 1];
                float w0 = hW_s[colb],   w1 = hW_s[colb + 1];
                pv0 += tanh_hw(c[mi][ni][0] + b0) * w0 + tanh_hw(c[mi][ni][1] + b1) * w1;
                pv1 += tanh_hw(c[mi][ni][2] + b0) * w0 + tanh_hw(c[mi][ni][3] + b1) * w1;
            }
            pv0 += __shfl_xor_sync(0xffffffffu, pv0, 1);
            pv0 += __shfl_xor_sync(0xffffffffu, pv0, 2);
            pv1 += __shfl_xor_sync(0xffffffffu, pv1, 1);
            pv1 += __shfl_xor_sync(0xffffffffu, pv1, 2);
            if (tq == 0) {
                int row = m0 + mbase + mi * 16 + g;
                atomicAdd(&g_values[row],     pv0);
                atomicAdd(&g_values[row + 8], pv1);
            }
        }
    } else {
        #pragma unroll
        for (int mi = 0; mi < 4; mi++) {
            float pm0[8] = {}, pm1[8] = {};
            #pragma unroll
            for (int ni = 0; ni < 4; ni++) {
                int colb = nbase + ni * 8 + 2 * tq;
                float b0 = bias_s[colb], b1 = bias_s[colb + 1];
                float t0 = tanh_hw(c[mi][ni][0] + b0);
                float t1 = tanh_hw(c[mi][ni][1] + b1);
                float t2 = tanh_hw(c[mi][ni][2] + b0);
                float t3 = tanh_hw(c[mi][ni][3] + b1);
                #pragma unroll
                for (int j = 0; j < 8; j++) {
                    float w0 = hW_s[colb * 8 + j], w1 = hW_s[(colb + 1) * 8 + j];
                    pm0[j] += t0 * w0 + t1 * w1;
                    pm1[j] += t2 * w0 + t3 * w1;
                }
            }
            #pragma unroll
            for (int j = 0; j < 8; j++) {
                pm0[j] += __shfl_xor_sync(0xffffffffu, pm0[j], 1);
                pm0[j] += __shfl_xor_sync(0xffffffffu, pm0[j], 2);
                pm1[j] += __shfl_xor_sync(0xffffffffu, pm1[j], 1);
                pm1[j] += __shfl_xor_sync(0xffffffffu, pm1[j], 2);
            }
            if (tq == 0) {
                int row = m0 + mbase + mi * 16 + g;
                #pragma unroll
                for (int j = 0; j < 8; j++) {
                    atomicAdd(&g_mu[(size_t)row * 8 + j],       pm0[j]);
                    atomicAdd(&g_mu[(size_t)(row + 8) * 8 + j], pm1[j]);
                }
            }
        }
    }
}

// ---------------- fused GAE scan + loss (128 blocks x 256 threads x 2 elems) ----------------
__global__ void __launch_bounds__(BTH) gae_loss(
    const float* __restrict__ r, const float* __restrict__ dmask,
    const float* __restrict__ a, const float* __restrict__ lpo,
    const float* __restrict__ logstd, float* __restrict__ out)
{
    const int gtid = blockIdx.x * BTH + threadIdx.x;
    const int u0   = gtid * EPT;               // thread handles u0, u0+1
    const int t0   = T - 1 - u0;               // element 0 -> t0, element 1 -> t0-1
    const int lane = threadIdx.x & 31, warp = threadIdx.x >> 5;   // 8 warps

    // ---- phase 1: per-thread 2-element composite, then block scan ----
    float m0v  = dmask[t0],      m1v = dmask[t0 - 1];
    float nv0  = g_values[t0 + 1], v0 = g_values[t0], v1 = g_values[t0 - 1];
    float r0   = r[t0],          r1  = r[t0 - 1];
    float b0e  = r0 + GAMMA_C * nv0 * m0v - v0;     // delta(u0)
    float a0e  = GL * m0v;
    float b1e  = r1 + GAMMA_C * v0 * m1v - v1;      // delta(u0+1): next value is v[t0]
    float a1e  = GL * m1v;
    // composite over [u0, u0+1]: g -> a1*(a0*g + b0) + b1
    float aa = a1e * a0e;
    float bb = fmaf(a1e, b0e, b1e);

    #pragma unroll
    for (int off = 1; off < 32; off <<= 1) {
        float ap = __shfl_up_sync(0xffffffffu, aa, off);
        float bp = __shfl_up_sync(0xffffffffu, bb, off);
        if (lane >= off) { bb = fmaf(aa, bp, bb); aa *= ap; }
    }
    __shared__ float wA[8], wB[8];
    if (lane == 31) { wA[warp] = aa; wB[warp] = bb; }
    __syncthreads();
    if (warp == 0 && lane < 8) {
        float a2 = wA[lane], b2 = wB[lane];
        #pragma unroll
        for (int off = 1; off < 8; off <<= 1) {
            float ap = __shfl_up_sync(0xffu, a2, off);
            float bp = __shfl_up_sync(0xffu, b2, off);
            if (lane >= off) { b2 = fmaf(a2, bp, b2); a2 *= ap; }
        }
        wA[lane] = a2; wB[lane] = b2;
    }
    __syncthreads();
    if (warp > 0) {
        float pa = wA[warp - 1], pb = wB[warp - 1];
        bb = fmaf(aa, pb, bb);
        aa *= pa;
    }
    if (threadIdx.x == BTH - 1) { g_Ablk[blockIdx.x] = aa; g_Bblk[blockIdx.x] = bb; }

    // ---- barrier 1: all block composites visible ----
    grid_barrier(&g_arr1, &g_dep1);

    __shared__ float ginS;
    if (threadIdx.x == 0) {
        float g = 0.f;
        for (int j = 0; j < blockIdx.x; j++) g = fmaf(g_Ablk[j], g, g_Bblk[j]);
        ginS = g;
    }
    __syncthreads();

    // thread-exclusive prefix: undo own contribution (gexc = (G_inclusive - bb)/aa would divide;
    // instead recompute via scan exclusive trick: inclusive from scan is (aa,bb) applied to ginS)
    // gexc for this thread = previous thread's inclusive; reconstruct from own: use shfl
    float ginc = fmaf(aa, ginS, bb);                 // g after this thread's 2 elements
    float gexc = __shfl_up_sync(0xffffffffu, ginc, 1);
    if (lane == 0) {
        // first lane of warp: exclusive = warp-prefix from wA/wB applied to ginS
        gexc = (warp > 0) ? fmaf(wA[warp - 1], ginS, wB[warp - 1]) : ginS;
    }
    const float adv0 = fmaf(a0e, gexc, b0e);         // adv at u0
    const float adv1 = fmaf(a1e, adv0, b1e);         // adv at u0+1

    // ---- phase 2: adv stats (both elements) ----
    __shared__ float rA[8], rB[8];
    {
        float s1 = adv0 + adv1, s2 = adv0 * adv0 + adv1 * adv1;
        #pragma unroll
        for (int o = 16; o; o >>= 1) {
            s1 += __shfl_down_sync(0xffffffffu, s1, o);
            s2 += __shfl_down_sync(0xffffffffu, s2, o);
        }
        if (lane == 0) { rA[warp] = s1; rB[warp] = s2; }
        __syncthreads();
        if (warp == 0 && lane < 8) {
            float t1 = rA[lane], t2 = rB[lane];
            #pragma unroll
            for (int o = 4; o; o >>= 1) {
                t1 += __shfl_down_sync(0xffu, t1, o);
                t2 += __shfl_down_sync(0xffu, t2, o);
            }
            if (lane == 0) {
                atomicAdd(&g_stats[0], t1);
                atomicAdd(&g_stats[1], t2);
            }
        }
        __syncthreads();
    }

    // ---- barrier 2: stats complete ----
    grid_barrier(&g_arr2, &g_dep2);

    float mean = g_stats[0] * (1.f / (float)T);
    float var  = (g_stats[1] - (float)T * mean * mean) * (1.f / (float)(T - 1));
    float sd   = sqrtf(fmaxf(var, 0.f));

    // ---- phase 3: loss terms for both elements (vectorized loads) ----
    float ls_c[A];
    #pragma unroll
    for (int j = 0; j < A; j++) ls_c[j] = logstd[j];

    float pgs = 0.f, vfs = 0.f;
    float advv[2] = {adv0, adv1};
    #pragma unroll
    for (int e = 0; e < EPT; e++) {
        int t = t0 - e;
        const float4* mup = (const float4*)(g_mu + (size_t)t * 8);
        const float4* ap4 = (const float4*)(a    + (size_t)t * 8);
        float4 mu0 = mup[0], mu1 = mup[1];
        float4 av0 = ap4[0], av1 = ap4[1];
        float muv[8] = {mu0.x, mu0.y, mu0.z, mu0.w, mu1.x, mu1.y, mu1.z, mu1.w};
        float av[8]  = {av0.x, av0.y, av0.z, av0.w, av1.x, av1.y, av1.z, av1.w};
        float lp = 0.f;
        #pragma unroll
        for (int j = 0; j < A; j++) {
            float d = (av[j] - muv[j]) * __expf(-ls_c[j]);
            lp += -0.5f * d * d - ls_c[j];
        }
        lp -= 0.5f * LOG2PI * (float)A;
        float rt = __expf(lp - lpo[t]);

        float adv  = advv[e];
        float advn = (adv - mean) / (sd + 1e-8f);
        float clip = fminf(fmaxf(rt, 1.f - EPSC), 1.f + EPSC);
        pgs += -fminf(rt * advn, clip * advn);
        float ax = fabsf(adv);
        vfs += (ax < 1.f) ? 0.5f * adv * adv : ax - 0.5f;
    }

    #pragma unroll
    for (int o = 16; o; o >>= 1) {
        pgs += __shfl_down_sync(0xffffffffu, pgs, o);
        vfs += __shfl_down_sync(0xffffffffu, vfs, o);
    }
    if (lane == 0) { rA[warp] = pgs; rB[warp] = vfs; }
    __syncthreads();
    if (warp == 0 && lane < 8) {
        float t1 = rA[lane], t2 = rB[lane];
        #pragma unroll
        for (int o = 4; o; o >>= 1) {
            t1 += __shfl_down_sync(0xffu, t1, o);
            t2 += __shfl_down_sync(0xffu, t2, o);
        }
        if (lane == 0) {
            atomicAdd(&g_stats[2], t1);
            atomicAdd(&g_stats[3], t2);
        }
    }
    __syncthreads();

    // ---- ticket finalize: last block to pass here sees all stat-atomics ----
    if (threadIdx.x == 0) {
        __threadfence();
        unsigned int tk = atomicAdd(&g_tick, 1u);
        if (tk == NBLK - 1) {
            float ent = 0.f;
            #pragma unroll
            for (int j = 0; j < A; j++) ent += 0.5f + 0.5f * LOG2PI + logstd[j];
            ent *= (1.f / (float)A);
            out[0] = g_stats[2] * (1.f / (float)T)
                   + 0.5f * g_stats[3] * (1.f / (float)T)
                   - 0.01f * ent;
            // reset accumulators + ticket for the next graph replay
            g_stats[0] = 0.f; g_stats[1] = 0.f; g_stats[2] = 0.f; g_stats[3] = 0.f;
            __threadfence();
            atomicExch(&g_tick, 0u);
        }
    }
}

// ---------------- launch ----------------
extern "C" void kernel_launch(void* const* d_in, const int* in_sizes, int n_in,
                              void* d_out, int out_size)
{
    const float* s_in  = (const float*)d_in[0];
    const float* a_in  = (const float*)d_in[1];
    const float* r_in  = (const float*)d_in[2];
    const float* sp_in = (const float*)d_in[3];
    const float* lpo   = (const float*)d_in[4];
    const float* dmask = (const float*)d_in[5];
    const float* piW1  = (const float*)d_in[6];
    const float* pib1  = (const float*)d_in[7];
    const float* piW2  = (const float*)d_in[8];
    const float* pib2  = (const float*)d_in[9];
    const float* muW   = (const float*)d_in[10];
    const float* mub   = (const float*)d_in[11];
    const float* lstd  = (const float*)d_in[12];
    const float* vW1   = (const float*)d_in[13];
    const float* vb1   = (const float*)d_in[14];
    const float* vW2   = (const float*)d_in[15];
    const float* vb2   = (const float*)d_in[16];
    const float* vhW   = (const float*)d_in[17];
    const float* vhb   = (const float*)d_in[18];
    float* out = (float*)d_out;

    cudaFuncSetAttribute(gemm_l1, cudaFuncAttributeMaxDynamicSharedMemorySize, SMEM_SZ);
    cudaFuncSetAttribute(gemm_l2, cudaFuncAttributeMaxDynamicSharedMemorySize, SMEM_SZ);

    // merged prep (input convert + weights + presets + bootstrap)
    prep_all<<<(T * S / 8) / 256, 256>>>(s_in, vW1, piW1, vW2, piW2, sp_in, vhb, mub);

    // layer 1: fused v+p, N=512, M includes bootstrap tile
    gemm_l1<<<dim3(4, T / 128 + 1), 256, SMEM_SZ>>>(vb1, pib1);
    // layer 2: merged v/p with fused heads (h2 never touches DRAM)
    gemm_l2<<<dim3(2, T / 128 + 1, 2), 256, SMEM_SZ>>>(vb2, pib2, vhW, muW);

    // fused GAE scan + normalization + PPO loss + finalize (one kernel)
    gae_loss<<<NBLK, BTH>>>(r_in, dmask, a_in, lpo, lstd, out);
}